// round 1
// baseline (speedup 1.0000x reference)
#include <cuda_runtime.h>
#include <cuda_bf16.h>
#include <math.h>

// ObservationEmbedding: out[b,t,:] = [ features[b,t,:] @ W^T + bias , pe(positions[t]) ]
// B=16384, T=64, F=16, Dh=128, D=256.
//
// Warp-per-t decomposition: each warp fixes t, computes pe once into registers,
// then streams over b writing 1 KB/row (two float4 stcs per lane).

#define TPB 256
#define WPB 8           // warps per block
#define NBLOCKS 8192    // total warps = 65536 -> 1024 warps per t

__global__ __launch_bounds__(TPB) void obs_embed_kernel(
    const float* __restrict__ features,   // [B,64,16]
    const float* __restrict__ W,          // [128,16] row-major
    const float* __restrict__ bias,       // [128]
    const int*   __restrict__ positions,  // [64]
    float*       __restrict__ out,        // [B,64,256]
    int B)
{
    __shared__ float Ws[16 * 128];  // Ws[k*128 + d] = W[d*16 + k]

    const int tid = threadIdx.x;
    #pragma unroll
    for (int idx = tid; idx < 16 * 128; idx += TPB) {
        int k = idx >> 7;
        int d = idx & 127;
        Ws[idx] = W[d * 16 + k];
    }
    __syncthreads();

    const int lane  = tid & 31;
    const int warp  = tid >> 5;
    const int gwarp = blockIdx.x * WPB + warp;
    const int t       = gwarp & 63;
    const int bStart  = gwarp >> 6;
    const int bStride = (gridDim.x * WPB) >> 6;

    // bias slice for this lane's 4 output columns (d = lane*4 .. lane*4+3)
    const float4 b4 = *reinterpret_cast<const float4*>(bias + lane * 4);

    // Positional embedding for this t, computed once.
    // pair j: pe[2j] = sin(pos * 10000^(-j/32)), pe[2j+1] = cos(...).
    // lane covers d = 4*lane..4*lane+3 -> pairs j0 = 2*lane, j1 = 2*lane+1.
    const int j0 = lane * 2;
    const int j1 = j0 + 1;
    const double pos = (double)positions[t];
    const double a0 = pos * pow(10000.0, -(double)j0 / 32.0);
    const double a1 = pos * pow(10000.0, -(double)j1 / 32.0);
    const float4 pe4 = make_float4((float)sin(a0), (float)cos(a0),
                                   (float)sin(a1), (float)cos(a1));

    for (int bb = bStart; bb < B; bb += bStride) {
        const long row = (long)bb * 64 + t;

        // 16 lanes fetch the 16-float feature row (one 64B segment), broadcast via shfl
        float f = 0.0f;
        if (lane < 16) f = __ldcs(features + row * 16 + lane);

        float4 acc = b4;
        #pragma unroll
        for (int k = 0; k < 16; ++k) {
            const float fk = __shfl_sync(0xffffffffu, f, k);
            const float4 w = *reinterpret_cast<const float4*>(Ws + k * 128 + lane * 4);
            acc.x = fmaf(fk, w.x, acc.x);
            acc.y = fmaf(fk, w.y, acc.y);
            acc.z = fmaf(fk, w.z, acc.z);
            acc.w = fmaf(fk, w.w, acc.w);
        }

        float* o = out + row * 256;
        __stcs(reinterpret_cast<float4*>(o + lane * 4),       acc);   // feature emb [0,128)
        __stcs(reinterpret_cast<float4*>(o + 128 + lane * 4), pe4);   // positional  [128,256)
    }
}

extern "C" void kernel_launch(void* const* d_in, const int* in_sizes, int n_in,
                              void* d_out, int out_size)
{
    const float* features  = (const float*)d_in[0];
    const float* W         = (const float*)d_in[1];
    const float* bias      = (const float*)d_in[2];
    const int*   positions = (const int*)d_in[3];
    float* out = (float*)d_out;

    const int B = in_sizes[0] / (64 * 16);

    obs_embed_kernel<<<NBLOCKS, TPB>>>(features, W, bias, positions, out, B);
}

// round 2
// speedup vs baseline: 2.3051x; 2.3051x over previous
#include <cuda_runtime.h>
#include <cstdint>

// out[b,t,:] = [ features[b,t,:] @ W^T + bias , pe(positions[t]) ]
// B=16384, T=64, F=16, Dh=128, D=256.  Output 1.07GB -> HBM-write-bound target.
//
// Unit = (b, half-t): 32 consecutive t rows. Features for a unit are 2KB
// CONTIGUOUS (t is the fast batch dim), outputs are 32KB contiguous.
// Per warp: cp.async double-buffered feature staging, W-reuse over 4-row
// t-blocks, pe from a precomputed table.

#define T_DIM 64
#define F_DIM 16
#define DH    128
#define TPB   512
#define WPB   (TPB / 32)
#define GRID  296

__device__ float g_pe[T_DIM * DH];

// Precompute sinusoidal positional embedding once (double precision; formula
// validated in round 1 at rel_err 5e-7).
__global__ void pe_kernel(const int* __restrict__ positions)
{
    int idx = blockIdx.x * blockDim.x + threadIdx.x;   // t*64 + j
    if (idx < T_DIM * (DH / 2)) {
        int t = idx >> 6;
        int j = idx & 63;
        double pos = (double)positions[t];
        // inv_freq = 10000^(-j/32) ; log2(10000) = 13.287712379549449
        double ang = pos * exp2(-(double)j * (13.287712379549449 / 32.0));
        double s, c;
        sincos(ang, &s, &c);
        g_pe[t * DH + 2 * j]     = (float)s;
        g_pe[t * DH + 2 * j + 1] = (float)c;
    }
}

__device__ __forceinline__ uint32_t smem_u32(const void* p)
{
    return (uint32_t)__cvta_generic_to_shared(p);
}

__device__ __forceinline__ void cp16(uint32_t dst, const void* src)
{
    asm volatile("cp.async.cg.shared.global [%0], [%1], 16;" :: "r"(dst), "l"(src));
}

__global__ __launch_bounds__(TPB, 2) void obs_embed_kernel(
    const float* __restrict__ features,   // [B,64,16]
    const float* __restrict__ W,          // [128,16]
    const float* __restrict__ bias,       // [128]
    float*       __restrict__ out,        // [B,64,256]
    int nUnits)                           // B*2
{
    __shared__ float  Ws[F_DIM][DH];          // 8KB, transposed: Ws[k][d]
    __shared__ float  pes[T_DIM * DH];        // 32KB
    __shared__ float4 fb[WPB][2][128];        // 64KB: per-warp double buffer, 2KB each

    const int tid = threadIdx.x;

    // Stage W transposed and pe table.
    for (int idx = tid; idx < F_DIM * DH; idx += TPB) {
        int k = idx >> 7, d = idx & 127;
        Ws[k][d] = W[d * F_DIM + k];
    }
    for (int idx = tid; idx < T_DIM * DH; idx += TPB)
        pes[idx] = g_pe[idx];
    __syncthreads();

    const int lane = tid & 31;
    const int warp = tid >> 5;
    const float4 bias4 = *reinterpret_cast<const float4*>(bias + lane * 4);

    const int gwarp   = blockIdx.x * WPB + warp;
    const int wstride = gridDim.x * WPB;

    int u = gwarp;

    // Prologue: prefetch unit u into buffer 0.
    if (u < nUnits) {
        const float4* src = reinterpret_cast<const float4*>(features) + (size_t)u * 128;
        uint32_t dst = smem_u32(&fb[warp][0][lane]);
        #pragma unroll
        for (int j = 0; j < 4; j++)
            cp16(dst + j * 32 * 16, src + j * 32 + lane);
    }
    asm volatile("cp.async.commit_group;");

    int p = 0;
    for (; u < nUnits; u += wstride, p ^= 1) {
        // Prefetch next unit into the other buffer.
        {
            int un = u + wstride;
            if (un < nUnits) {
                const float4* src = reinterpret_cast<const float4*>(features) + (size_t)un * 128;
                uint32_t dst = smem_u32(&fb[warp][p ^ 1][lane]);
                #pragma unroll
                for (int j = 0; j < 4; j++)
                    cp16(dst + j * 32 * 16, src + j * 32 + lane);
            }
            asm volatile("cp.async.commit_group;");
        }
        // Current unit's group (committed last iteration / prologue) must be done.
        asm volatile("cp.async.wait_group 1;");
        __syncwarp();

        const float* fcur = reinterpret_cast<const float*>(fb[warp][p]);  // [32][16]
        const int b  = u >> 1;
        const int t0 = (u & 1) * 32;
        float* obase = out + ((size_t)b * T_DIM + t0) * (2 * DH);

        #pragma unroll
        for (int tb = 0; tb < 32; tb += 4) {
            float4 a0 = bias4, a1 = bias4, a2 = bias4, a3 = bias4;

            #pragma unroll
            for (int kc = 0; kc < 4; kc++) {
                const float4 w0 = *reinterpret_cast<const float4*>(&Ws[kc * 4 + 0][lane * 4]);
                const float4 w1 = *reinterpret_cast<const float4*>(&Ws[kc * 4 + 1][lane * 4]);
                const float4 w2 = *reinterpret_cast<const float4*>(&Ws[kc * 4 + 2][lane * 4]);
                const float4 w3 = *reinterpret_cast<const float4*>(&Ws[kc * 4 + 3][lane * 4]);

                #define ROWFMA(ACC, ROW)                                                        \
                {                                                                               \
                    const float4 f = *reinterpret_cast<const float4*>(                          \
                        fcur + (tb + (ROW)) * F_DIM + kc * 4);                                  \
                    ACC.x = fmaf(f.x, w0.x, ACC.x); ACC.y = fmaf(f.x, w0.y, ACC.y);             \
                    ACC.z = fmaf(f.x, w0.z, ACC.z); ACC.w = fmaf(f.x, w0.w, ACC.w);             \
                    ACC.x = fmaf(f.y, w1.x, ACC.x); ACC.y = fmaf(f.y, w1.y, ACC.y);             \
                    ACC.z = fmaf(f.y, w1.z, ACC.z); ACC.w = fmaf(f.y, w1.w, ACC.w);             \
                    ACC.x = fmaf(f.z, w2.x, ACC.x); ACC.y = fmaf(f.z, w2.y, ACC.y);             \
                    ACC.z = fmaf(f.z, w2.z, ACC.z); ACC.w = fmaf(f.z, w2.w, ACC.w);             \
                    ACC.x = fmaf(f.w, w3.x, ACC.x); ACC.y = fmaf(f.w, w3.y, ACC.y);             \
                    ACC.z = fmaf(f.w, w3.z, ACC.z); ACC.w = fmaf(f.w, w3.w, ACC.w);             \
                }
                ROWFMA(a0, 0)
                ROWFMA(a1, 1)
                ROWFMA(a2, 2)
                ROWFMA(a3, 3)
                #undef ROWFMA
            }

            // Store 4 rows: feature half from acc, pe half from the smem table.
            #pragma unroll
            for (int r = 0; r < 4; r++) {
                const float4 pe4 = *reinterpret_cast<const float4*>(
                    &pes[(t0 + tb + r) * DH + lane * 4]);
                float4* o = reinterpret_cast<float4*>(obase + (size_t)(tb + r) * (2 * DH));
                const float4 a = (r == 0) ? a0 : (r == 1) ? a1 : (r == 2) ? a2 : a3;
                __stcs(o + lane, a);
                __stcs(o + 32 + lane, pe4);
            }
        }
    }
}

extern "C" void kernel_launch(void* const* d_in, const int* in_sizes, int n_in,
                              void* d_out, int out_size)
{
    const float* features  = (const float*)d_in[0];
    const float* W         = (const float*)d_in[1];
    const float* bias      = (const float*)d_in[2];
    const int*   positions = (const int*)d_in[3];
    float* out = (float*)d_out;

    const int B = in_sizes[0] / (T_DIM * F_DIM);

    pe_kernel<<<8, 512>>>(positions);
    obs_embed_kernel<<<GRID, TPB>>>(features, W, bias, out, B * 2);
}

// round 3
// speedup vs baseline: 7.8510x; 3.4060x over previous
#include <cuda_runtime.h>
#include <cstdint>

// out[b,t,:] = [ features[b,t,:] @ W^T + bias , pe(positions[t]) ]
// B=16384, T=64, F=16, Dh=128. Output = 32768 contiguous 32KB "units".
//
// Per block: compute feature-emb halves of a 32-row unit into smem staging
// (pe halves written once — constant per block), then TMA bulk-store the
// 32KB tile. 296 big sequential write streams instead of 4736 x 1KB ones.

#define T_DIM 64
#define F_DIM 16
#define DH    128
#define GRID  296          // even -> unit parity fixed per block
#define TPB   256
#define STG_FLOATS  8192   // 32 rows * 256 cols
#define SMEM_BYTES  (2 * STG_FLOATS * 4 + 2 * 32 * 16 * 4)   // 69632

__device__ float g_pe[T_DIM * DH];

__global__ void pe_kernel(const int* __restrict__ positions)
{
    int idx = blockIdx.x * blockDim.x + threadIdx.x;   // t*64 + j
    if (idx < T_DIM * (DH / 2)) {
        int t = idx >> 6;
        int j = idx & 63;
        double pos = (double)positions[t];
        double ang = pos * exp2(-(double)j * (13.287712379549449 / 32.0));
        double s, c;
        sincos(ang, &s, &c);
        g_pe[t * DH + 2 * j]     = (float)s;
        g_pe[t * DH + 2 * j + 1] = (float)c;
    }
}

__device__ __forceinline__ uint32_t smem_u32(const void* p)
{
    return (uint32_t)__cvta_generic_to_shared(p);
}
__device__ __forceinline__ void cp16(uint32_t dst, const void* src)
{
    asm volatile("cp.async.cg.shared.global [%0], [%1], 16;" :: "r"(dst), "l"(src));
}
__device__ __forceinline__ unsigned long long pack2(float a, float b)
{
    unsigned long long r;
    asm("mov.b64 %0, {%1, %2};" : "=l"(r) : "f"(a), "f"(b));
    return r;
}
__device__ __forceinline__ void fma2(unsigned long long& d,
                                     unsigned long long a, unsigned long long b)
{
    asm("fma.rn.f32x2 %0, %1, %2, %0;" : "+l"(d) : "l"(a), "l"(b));
}

__global__ __launch_bounds__(TPB, 2) void obs_embed_kernel(
    const float* __restrict__ features,   // [B,64,16]
    const float* __restrict__ W,          // [128,16]
    const float* __restrict__ bias,       // [128]
    float*       __restrict__ out,        // [B,64,256]
    int nUnits)                           // B*2
{
    extern __shared__ float smem[];
    float* stg0 = smem;                   // [32][256] staging, buffer 0
    float* stg1 = smem + STG_FLOATS;      // buffer 1
    float* ffb  = smem + 2 * STG_FLOATS;  // [2][32][16] feature staging

    const int tid  = threadIdx.x;
    const int lane = tid & 31;
    const int warp = tid >> 5;

    // pe halves of both staging buffers: constant for this block (unit
    // parity = blockIdx parity since GRID is even).
    const int t0 = (blockIdx.x & 1) * 32;
    for (int idx = tid; idx < 32 * DH; idx += TPB) {
        int r = idx >> 7, c = idx & 127;
        float v = g_pe[(t0 + r) * DH + c];
        stg0[r * 256 + DH + c] = v;
        stg1[r * 256 + DH + c] = v;
    }

    // W into packed registers. Lane owns output cols d = 4*lane + {0..3}.
    // wp0[k] = {W[d0][k], W[d1][k]},  wp1[k] = {W[d2][k], W[d3][k]}.
    unsigned long long wp0[16], wp1[16];
    {
        const float4* Wv = reinterpret_cast<const float4*>(W);
        #pragma unroll
        for (int q = 0; q < 4; ++q) {
            float4 w0 = Wv[(4 * lane + 0) * 4 + q];
            float4 w1 = Wv[(4 * lane + 1) * 4 + q];
            float4 w2 = Wv[(4 * lane + 2) * 4 + q];
            float4 w3 = Wv[(4 * lane + 3) * 4 + q];
            wp0[4*q+0] = pack2(w0.x, w1.x);  wp1[4*q+0] = pack2(w2.x, w3.x);
            wp0[4*q+1] = pack2(w0.y, w1.y);  wp1[4*q+1] = pack2(w2.y, w3.y);
            wp0[4*q+2] = pack2(w0.z, w1.z);  wp1[4*q+2] = pack2(w2.z, w3.z);
            wp0[4*q+3] = pack2(w0.w, w1.w);  wp1[4*q+3] = pack2(w2.w, w3.w);
        }
    }
    const unsigned long long bp0 = pack2(bias[4 * lane + 0], bias[4 * lane + 1]);
    const unsigned long long bp1 = pack2(bias[4 * lane + 2], bias[4 * lane + 3]);

    int u = blockIdx.x;
    // Prologue: prefetch unit u features (warp w owns its 4 rows, 256B).
    if (u < nUnits && lane < 16)
        cp16(smem_u32(ffb + warp * 64 + lane * 4),
             features + (size_t)u * 512 + warp * 64 + lane * 4);
    asm volatile("cp.async.commit_group;");

    int p = 0;
    for (; u < nUnits; u += GRID, p ^= 1) {
        // Reuse gate: TMA smem-read of buffer p (issued 2 iters ago) done.
        if (tid == 0) asm volatile("cp.async.bulk.wait_group.read 1;");
        __syncthreads();

        // Prefetch next unit's features into the other buffer.
        int un = u + GRID;
        if (un < nUnits && lane < 16)
            cp16(smem_u32(ffb + (p ^ 1) * 512 + warp * 64 + lane * 4),
                 features + (size_t)un * 512 + warp * 64 + lane * 4);
        asm volatile("cp.async.commit_group;");
        // Current features (committed last iter / prologue) ready.
        asm volatile("cp.async.wait_group 1;");
        __syncwarp();

        float* stg = p ? stg1 : stg0;
        const float* fcur = ffb + p * 512 + warp * 64;   // this warp's 4 rows

        #pragma unroll
        for (int rr = 0; rr < 4; ++rr) {
            const float4* frow = reinterpret_cast<const float4*>(fcur + rr * 16);
            unsigned long long a0 = bp0, a1 = bp1;
            #pragma unroll
            for (int q = 0; q < 4; ++q) {
                const float4 f = frow[q];   // broadcast LDS, conflict-free
                unsigned long long ff;
                ff = pack2(f.x, f.x); fma2(a0, ff, wp0[4*q+0]); fma2(a1, ff, wp1[4*q+0]);
                ff = pack2(f.y, f.y); fma2(a0, ff, wp0[4*q+1]); fma2(a1, ff, wp1[4*q+1]);
                ff = pack2(f.z, f.z); fma2(a0, ff, wp0[4*q+2]); fma2(a1, ff, wp1[4*q+2]);
                ff = pack2(f.w, f.w); fma2(a0, ff, wp0[4*q+3]); fma2(a1, ff, wp1[4*q+3]);
            }
            uint32_t sa = smem_u32(stg + (warp * 4 + rr) * 256 + lane * 4);
            asm volatile("st.shared.v2.u64 [%0], {%1, %2};"
                         :: "r"(sa), "l"(a0), "l"(a1));
        }
        __syncthreads();

        if (tid == 0) {
            asm volatile("fence.proxy.async.shared::cta;");
            asm volatile(
                "cp.async.bulk.global.shared::cta.bulk_group [%0], [%1], %2;"
                :: "l"(out + (size_t)u * STG_FLOATS / 2 * 2),   // u * 8192 floats
                   "r"(smem_u32(stg)), "r"(32768) : "memory");
            asm volatile("cp.async.bulk.commit_group;");
        }
    }
    // Drain outstanding bulk stores before exit.
    asm volatile("cp.async.bulk.wait_group 0;");
}

extern "C" void kernel_launch(void* const* d_in, const int* in_sizes, int n_in,
                              void* d_out, int out_size)
{
    const float* features  = (const float*)d_in[0];
    const float* W         = (const float*)d_in[1];
    const float* bias      = (const float*)d_in[2];
    const int*   positions = (const int*)d_in[3];
    float* out = (float*)d_out;

    const int B = in_sizes[0] / (T_DIM * F_DIM);

    cudaFuncSetAttribute(obs_embed_kernel,
                         cudaFuncAttributeMaxDynamicSharedMemorySize, SMEM_BYTES);

    pe_kernel<<<8, 512>>>(positions);
    obs_embed_kernel<<<GRID, TPB, SMEM_BYTES>>>(features, W, bias, out, B * 2);
}